// round 1
// baseline (speedup 1.0000x reference)
#include <cuda_runtime.h>

// Problem constants (fixed by the reference)
#define NN   50000
#define EE   1600000
#define FIN  512
#define FHID 256
#define FOUT 128
#define EPSF 1e-5f

#define NBLK_STATS 1024
#define SCAN_B 1024
#define NSCAN  ((NN + SCAN_B - 1) / SCAN_B)   // 49

// ---------------- device scratch (static, allocation-free) ----------------
__device__ float g_h1pre[(size_t)NN * FHID];
__device__ float g_h1   [(size_t)NN * FHID];
__device__ float g_h2pre[(size_t)NN * FOUT];
__device__ float g_h2   [(size_t)NN * FOUT];
__device__ int   g_colsrc[EE];
__device__ float g_colw  [EE];
__device__ int   g_deg   [NN];
__device__ float g_dinv  [NN];
__device__ int   g_rowptr[NN + 1];
__device__ int   g_cursor[NN];
__device__ int   g_blocksum[64];
__device__ int   g_blockoff[64];
__device__ float g_ps [NBLK_STATS];
__device__ float g_pss[NBLK_STATS];
__device__ float g_a[FIN];   // per-k LN affine scale (max K = 512)
__device__ float g_c[FIN];   // per-k LN affine shift
__device__ float g_colsum[FOUT];
__device__ float g_ss2;

// ---------------- init: reset accumulators every replay ----------------
__global__ void k_init() {
    int i = blockIdx.x * blockDim.x + threadIdx.x;
    if (i < NN) g_deg[i] = 1;                 // self-loop
    if (i < FOUT) g_colsum[i] = 0.f;
    if (i == FOUT) g_ss2 = 0.f;
}

// ---------------- sum / sumsq partials (vectorized grid-stride) ----------------
template <bool FROM_H1>
__global__ void k_stats(const float* __restrict__ p_in, int n4) {
    const float* __restrict__ p = FROM_H1 ? (const float*)g_h1 : p_in;
    float s = 0.f, ss = 0.f;
    int stride = gridDim.x * blockDim.x;
    for (int i = blockIdx.x * blockDim.x + threadIdx.x; i < n4; i += stride) {
        float4 v = ((const float4*)p)[i];
        s  += v.x + v.y + v.z + v.w;
        ss += v.x * v.x + v.y * v.y + v.z * v.z + v.w * v.w;
    }
    __shared__ float sh[256], sh2[256];
    sh[threadIdx.x] = s; sh2[threadIdx.x] = ss;
    __syncthreads();
    for (int o = 128; o > 0; o >>= 1) {
        if (threadIdx.x < o) { sh[threadIdx.x] += sh[threadIdx.x + o]; sh2[threadIdx.x] += sh2[threadIdx.x + o]; }
        __syncthreads();
    }
    if (threadIdx.x == 0) { g_ps[blockIdx.x] = sh[0]; g_pss[blockIdx.x] = sh2[0]; }
}

// ---------------- finalize LN stats -> per-k affine a,c ----------------
__global__ void k_finalize_ln(float invM, const float* __restrict__ w,
                              const float* __restrict__ b, int K) {
    __shared__ float sh[256], sh2[256];
    int tid = threadIdx.x;
    float s = 0.f, ss = 0.f;
    for (int i = tid; i < NBLK_STATS; i += 256) { s += g_ps[i]; ss += g_pss[i]; }
    sh[tid] = s; sh2[tid] = ss;
    __syncthreads();
    for (int o = 128; o > 0; o >>= 1) {
        if (tid < o) { sh[tid] += sh[tid + o]; sh2[tid] += sh2[tid + o]; }
        __syncthreads();
    }
    __shared__ float smean, srs;
    if (tid == 0) {
        float mean = sh[0] * invM;
        float var  = sh2[0] * invM - mean * mean;
        smean = mean;
        srs = rsqrtf(var + EPSF);
    }
    __syncthreads();
    for (int k = tid; k < K; k += 256) {
        float wk = w[k];
        g_a[k] = srs * wk;
        g_c[k] = fmaf(-srs * smean, wk, b[k]);
    }
}

// ---------------- degree histogram / dinv ----------------
__global__ void k_deg(const int* __restrict__ dst) {
    int e = blockIdx.x * blockDim.x + threadIdx.x;
    if (e < EE) atomicAdd(&g_deg[dst[e]], 1);
}
__global__ void k_dinv() {
    int n = blockIdx.x * blockDim.x + threadIdx.x;
    if (n < NN) g_dinv[n] = rsqrtf((float)g_deg[n]);
}

// ---------------- exclusive scan over in-degree counts -> row_ptr ----------------
__global__ void k_scan1() {
    __shared__ int s[SCAN_B];
    int tid = threadIdx.x;
    int n = blockIdx.x * SCAN_B + tid;
    int cnt = (n < NN) ? (g_deg[n] - 1) : 0;   // exclude self-loop
    s[tid] = cnt;
    __syncthreads();
    for (int off = 1; off < SCAN_B; off <<= 1) {
        int v = (tid >= off) ? s[tid - off] : 0;
        __syncthreads();
        s[tid] += v;
        __syncthreads();
    }
    if (n < NN) g_rowptr[n] = s[tid] - cnt;     // exclusive
    if (tid == SCAN_B - 1) g_blocksum[blockIdx.x] = s[SCAN_B - 1];
}
__global__ void k_scan2(int nb) {
    if (threadIdx.x == 0) {
        int acc = 0;
        for (int b = 0; b < nb; b++) { g_blockoff[b] = acc; acc += g_blocksum[b]; }
    }
}
__global__ void k_scan3() {
    int n = blockIdx.x * blockDim.x + threadIdx.x;
    if (n < NN) {
        int r = g_rowptr[n] + g_blockoff[n >> 10];
        g_rowptr[n] = r;
        g_cursor[n] = r;
    }
    if (n == 0) g_rowptr[NN] = EE;
}

// ---------------- CSR scatter: edges sorted by dst, precompute edge weight ----------------
__global__ void k_scatter(const int* __restrict__ src, const int* __restrict__ dst) {
    int e = blockIdx.x * blockDim.x + threadIdx.x;
    if (e < EE) {
        int d = dst[e], s = src[e];
        int pos = atomicAdd(&g_cursor[d], 1);
        g_colsrc[pos] = s;
        g_colw[pos]   = g_dinv[s] * g_dinv[d];
    }
}

// ---------------- GEMM with fused LN affine on input: Y = (a.*X + c) @ W ----------------
// BM=128, BN=128, BK=8, 256 threads, 8x8 per thread.
template <int K_, int N_, bool X_FROM_H1>
__global__ __launch_bounds__(256) void k_gemm(const float* __restrict__ Xin,
                                              const float* __restrict__ W) {
    constexpr int BM = 128, BN = 128, BK = 8;
    __shared__ float As[BK][BM];
    __shared__ float Bs[BK][BN];
    __shared__ float sA[K_], sC[K_];

    const float* __restrict__ X = X_FROM_H1 ? (const float*)g_h1 : Xin;
    float* __restrict__ Y = X_FROM_H1 ? (float*)g_h2pre : (float*)g_h1pre;

    int tid = threadIdx.x;
    for (int i = tid; i < K_; i += 256) { sA[i] = g_a[i]; sC[i] = g_c[i]; }

    int bx = blockIdx.x, by = blockIdx.y;
    int aRow = tid >> 1, aCol = (tid & 1) * 4;
    int bRow = tid >> 5, bCol = (tid & 31) * 4;
    int tr = (tid >> 4) * 8, tc = (tid & 15) * 8;

    int rowA = by * BM + aRow;
    bool aok = rowA < NN;
    const float* Xrow = X + (size_t)rowA * K_;

    float acc[8][8] = {};
    __syncthreads();  // sA/sC ready

    for (int k0 = 0; k0 < K_; k0 += BK) {
        float4 av = aok ? *(const float4*)(Xrow + k0 + aCol) : make_float4(0.f, 0.f, 0.f, 0.f);
        As[aCol + 0][aRow] = fmaf(sA[k0 + aCol + 0], av.x, sC[k0 + aCol + 0]);
        As[aCol + 1][aRow] = fmaf(sA[k0 + aCol + 1], av.y, sC[k0 + aCol + 1]);
        As[aCol + 2][aRow] = fmaf(sA[k0 + aCol + 2], av.z, sC[k0 + aCol + 2]);
        As[aCol + 3][aRow] = fmaf(sA[k0 + aCol + 3], av.w, sC[k0 + aCol + 3]);

        float4 bv = *(const float4*)(W + (size_t)(k0 + bRow) * N_ + bx * BN + bCol);
        *(float4*)&Bs[bRow][bCol] = bv;
        __syncthreads();

#pragma unroll
        for (int k = 0; k < BK; k++) {
            float ra[8], rb[8];
#pragma unroll
            for (int i = 0; i < 8; i++) ra[i] = As[k][tr + i];
#pragma unroll
            for (int j = 0; j < 8; j++) rb[j] = Bs[k][tc + j];
#pragma unroll
            for (int i = 0; i < 8; i++)
#pragma unroll
                for (int j = 0; j < 8; j++)
                    acc[i][j] = fmaf(ra[i], rb[j], acc[i][j]);
        }
        __syncthreads();
    }

#pragma unroll
    for (int i = 0; i < 8; i++) {
        int gm = by * BM + tr + i;
        if (gm < NN) {
            float* yr = Y + (size_t)gm * N_ + bx * BN + tc;
            *(float4*)yr       = make_float4(acc[i][0], acc[i][1], acc[i][2], acc[i][3]);
            *(float4*)(yr + 4) = make_float4(acc[i][4], acc[i][5], acc[i][6], acc[i][7]);
        }
    }
}

// ---------------- aggregation: one block per dst node, no output atomics ----------------
template <int F, bool SECOND>
__global__ void k_agg(const float* __restrict__ bias) {
    const float* __restrict__ hpre = SECOND ? (const float*)g_h2pre : (const float*)g_h1pre;
    float* __restrict__ hout       = SECOND ? (float*)g_h2 : (float*)g_h1;

    int n = blockIdx.x;
    int f = threadIdx.x;
    float di = g_dinv[n];
    float acc = di * di * hpre[(size_t)n * F + f];

    int e = g_rowptr[n];
    int end = g_rowptr[n + 1];
    for (; e + 4 <= end; e += 4) {
        int s0 = g_colsrc[e + 0], s1 = g_colsrc[e + 1];
        int s2 = g_colsrc[e + 2], s3 = g_colsrc[e + 3];
        float w0 = g_colw[e + 0], w1 = g_colw[e + 1];
        float w2 = g_colw[e + 2], w3 = g_colw[e + 3];
        float v0 = hpre[(size_t)s0 * F + f];
        float v1 = hpre[(size_t)s1 * F + f];
        float v2 = hpre[(size_t)s2 * F + f];
        float v3 = hpre[(size_t)s3 * F + f];
        acc = fmaf(w0, v0, acc);
        acc = fmaf(w1, v1, acc);
        acc = fmaf(w2, v2, acc);
        acc = fmaf(w3, v3, acc);
    }
    for (; e < end; ++e)
        acc = fmaf(g_colw[e], hpre[(size_t)g_colsrc[e] * F + f], acc);

    hout[(size_t)n * F + f] = fmaxf(acc + bias[f], 0.f);
}

// ---------------- reduce h2: column sums + global sumsq ----------------
__global__ void k_reduce_h2() {
    int tid = threadIdx.x;
    float col = 0.f, ss = 0.f;
    int stride = gridDim.x * 256;     // multiple of 128 -> fixed channel per thread
    for (int i = blockIdx.x * 256 + tid; i < NN * FOUT; i += stride) {
        float v = g_h2[i];
        col += v;
        ss += v * v;
    }
    __shared__ float shc[256], shs[256];
    shc[tid] = col; shs[tid] = ss;
    __syncthreads();
    if (tid < 128) shc[tid] += shc[tid + 128];  // same channel pairing
    for (int o = 128; o > 0; o >>= 1) {
        if (tid < o) shs[tid] += shs[tid + o];
        __syncthreads();
    }
    if (tid < 128) atomicAdd(&g_colsum[tid], shc[tid]);
    if (tid == 0)  atomicAdd(&g_ss2, shs[0]);
}

// ---------------- final LN2 + global mean pool -> out[1,128] ----------------
__global__ void k_final(const float* __restrict__ w, const float* __restrict__ b,
                        float* __restrict__ out) {
    __shared__ float sh[128];
    int tid = threadIdx.x;
    float cs = g_colsum[tid];
    sh[tid] = cs;
    __syncthreads();
    for (int o = 64; o > 0; o >>= 1) {
        if (tid < o) sh[tid] += sh[tid + o];
        __syncthreads();
    }
    float invM = 1.f / (float)((size_t)NN * FOUT);
    float mean = sh[0] * invM;
    float var  = g_ss2 * invM - mean * mean;
    float rs   = rsqrtf(var + EPSF);
    out[tid] = (cs * (1.f / (float)NN) - mean) * rs * w[tid] + b[tid];
}

// ---------------- launch ----------------
extern "C" void kernel_launch(void* const* d_in, const int* in_sizes, int n_in,
                              void* d_out, int out_size) {
    const float* x    = (const float*)d_in[0];
    const int*   ei   = (const int*)d_in[1];
    const float* W1   = (const float*)d_in[2];
    const float* b1   = (const float*)d_in[3];
    const float* W2   = (const float*)d_in[4];
    const float* b2   = (const float*)d_in[5];
    const float* ln0w = (const float*)d_in[6];
    const float* ln0b = (const float*)d_in[7];
    const float* ln1w = (const float*)d_in[8];
    const float* ln1b = (const float*)d_in[9];
    const float* ln2w = (const float*)d_in[10];
    const float* ln2b = (const float*)d_in[11];
    const int* src = ei;
    const int* dst = ei + EE;
    float* out = (float*)d_out;

    dim3 nb256((NN + 255) / 256, 1, 1);
    dim3 eb256((EE + 255) / 256, 1, 1);

    // init + ln0 stats + graph structure
    k_init<<<nb256, 256>>>();
    k_stats<false><<<NBLK_STATS, 256>>>(x, (NN * FIN) / 4);
    k_deg<<<eb256, 256>>>(dst);
    k_dinv<<<nb256, 256>>>();
    k_finalize_ln<<<1, 256>>>(1.f / (float)((size_t)NN * FIN), ln0w, ln0b, FIN);
    k_scan1<<<NSCAN, SCAN_B>>>();
    k_scan2<<<1, 32>>>(NSCAN);
    k_scan3<<<nb256, 256>>>();
    k_scatter<<<eb256, 256>>>(src, dst);

    // layer 1: (ln0(x)) @ W1  ->  aggregate + bias + relu
    k_gemm<FIN, FHID, false><<<dim3(FHID / 128, (NN + 127) / 128), 256>>>(x, W1);
    k_agg<FHID, false><<<NN, FHID>>>(b1);

    // ln1 stats -> affine for GEMM2
    k_stats<true><<<NBLK_STATS, 256>>>(nullptr, (NN * FHID) / 4);
    k_finalize_ln<<<1, 256>>>(1.f / (float)((size_t)NN * FHID), ln1w, ln1b, FHID);

    // layer 2: (ln1(h1)) @ W2 -> aggregate + bias + relu
    k_gemm<FHID, FOUT, true><<<dim3(FOUT / 128, (NN + 127) / 128), 256>>>(nullptr, W2);
    k_agg<FOUT, true><<<NN, FOUT>>>(b2);

    // ln2 + mean pool
    k_reduce_h2<<<512, 256>>>();
    k_final<<<1, FOUT>>>(ln2w, ln2b, out);
}

// round 2
// speedup vs baseline: 2.0038x; 2.0038x over previous
#include <cuda_runtime.h>
#include <cstdint>

// Problem constants (fixed by the reference)
#define NN   50000
#define EE   1600000
#define FIN  512
#define FHID 256
#define FOUT 128
#define EPSF 1e-5f

#define NBLK_STATS 1024
#define SCAN_B 1024
#define NSCAN  ((NN + SCAN_B - 1) / SCAN_B)   // 49

// ---------------- device scratch (static, allocation-free) ----------------
__device__ float g_h1pre[(size_t)NN * FHID];
__device__ float g_h1   [(size_t)NN * FHID];
__device__ float g_h2pre[(size_t)NN * FOUT];
__device__ float g_h2   [(size_t)NN * FOUT];
__device__ int   g_colsrc[EE];
__device__ float g_colw  [EE];
__device__ int   g_deg   [NN];
__device__ float g_dinv  [NN];
__device__ int   g_rowptr[NN + 1];
__device__ int   g_cursor[NN];
__device__ int   g_blocksum[64];
__device__ int   g_blockoff[64];
__device__ float g_ps [NBLK_STATS];
__device__ float g_pss[NBLK_STATS];
__device__ float g_a[FIN];   // per-k LN affine scale (max K = 512)
__device__ float g_c[FIN];   // per-k LN affine shift
__device__ float g_colsum[FOUT];
__device__ float g_ss2;

// ---------------- helpers ----------------
__device__ __forceinline__ uint32_t f2tf32(float f) {
    uint32_t u;
    asm("cvt.rna.tf32.f32 %0, %1;" : "=r"(u) : "f"(f));
    return u;
}

__device__ __forceinline__ void mma_tf32(float c[4], uint32_t a0, uint32_t a1,
                                         uint32_t a2, uint32_t a3,
                                         uint32_t b0, uint32_t b1) {
    asm volatile(
        "mma.sync.aligned.m16n8k8.row.col.f32.tf32.tf32.f32 "
        "{%0,%1,%2,%3}, {%4,%5,%6,%7}, {%8,%9}, {%0,%1,%2,%3};"
        : "+f"(c[0]), "+f"(c[1]), "+f"(c[2]), "+f"(c[3])
        : "r"(a0), "r"(a1), "r"(a2), "r"(a3), "r"(b0), "r"(b1));
}

// ---------------- init: reset accumulators every replay ----------------
__global__ void k_init() {
    int i = blockIdx.x * blockDim.x + threadIdx.x;
    if (i < NN) g_deg[i] = 1;                 // self-loop
    if (i < FOUT) g_colsum[i] = 0.f;
    if (i == FOUT) g_ss2 = 0.f;
}

// ---------------- sum / sumsq partials (vectorized grid-stride) ----------------
template <bool FROM_H1>
__global__ void k_stats(const float* __restrict__ p_in, int n4) {
    const float* __restrict__ p = FROM_H1 ? (const float*)g_h1 : p_in;
    float s = 0.f, ss = 0.f;
    int stride = gridDim.x * blockDim.x;
    for (int i = blockIdx.x * blockDim.x + threadIdx.x; i < n4; i += stride) {
        float4 v = ((const float4*)p)[i];
        s  += v.x + v.y + v.z + v.w;
        ss += v.x * v.x + v.y * v.y + v.z * v.z + v.w * v.w;
    }
    __shared__ float sh[256], sh2[256];
    sh[threadIdx.x] = s; sh2[threadIdx.x] = ss;
    __syncthreads();
    for (int o = 128; o > 0; o >>= 1) {
        if (threadIdx.x < o) { sh[threadIdx.x] += sh[threadIdx.x + o]; sh2[threadIdx.x] += sh2[threadIdx.x + o]; }
        __syncthreads();
    }
    if (threadIdx.x == 0) { g_ps[blockIdx.x] = sh[0]; g_pss[blockIdx.x] = sh2[0]; }
}

// ---------------- finalize LN stats -> per-k affine a,c ----------------
__global__ void k_finalize_ln(float invM, const float* __restrict__ w,
                              const float* __restrict__ b, int K) {
    __shared__ float sh[256], sh2[256];
    int tid = threadIdx.x;
    float s = 0.f, ss = 0.f;
    for (int i = tid; i < NBLK_STATS; i += 256) { s += g_ps[i]; ss += g_pss[i]; }
    sh[tid] = s; sh2[tid] = ss;
    __syncthreads();
    for (int o = 128; o > 0; o >>= 1) {
        if (tid < o) { sh[tid] += sh[tid + o]; sh2[tid] += sh2[tid + o]; }
        __syncthreads();
    }
    __shared__ float smean, srs;
    if (tid == 0) {
        float mean = sh[0] * invM;
        float var  = sh2[0] * invM - mean * mean;
        smean = mean;
        srs = rsqrtf(var + EPSF);
    }
    __syncthreads();
    for (int k = tid; k < K; k += 256) {
        float wk = w[k];
        g_a[k] = srs * wk;
        g_c[k] = fmaf(-srs * smean, wk, b[k]);
    }
}

// ---------------- degree histogram / dinv ----------------
__global__ void k_deg(const int* __restrict__ dst) {
    int e = blockIdx.x * blockDim.x + threadIdx.x;
    if (e < EE) atomicAdd(&g_deg[dst[e]], 1);
}
__global__ void k_dinv() {
    int n = blockIdx.x * blockDim.x + threadIdx.x;
    if (n < NN) g_dinv[n] = rsqrtf((float)g_deg[n]);
}

// ---------------- exclusive scan over in-degree counts -> row_ptr ----------------
__global__ void k_scan1() {
    __shared__ int s[SCAN_B];
    int tid = threadIdx.x;
    int n = blockIdx.x * SCAN_B + tid;
    int cnt = (n < NN) ? (g_deg[n] - 1) : 0;   // exclude self-loop
    s[tid] = cnt;
    __syncthreads();
    for (int off = 1; off < SCAN_B; off <<= 1) {
        int v = (tid >= off) ? s[tid - off] : 0;
        __syncthreads();
        s[tid] += v;
        __syncthreads();
    }
    if (n < NN) g_rowptr[n] = s[tid] - cnt;     // exclusive
    if (tid == SCAN_B - 1) g_blocksum[blockIdx.x] = s[SCAN_B - 1];
}
__global__ void k_scan2(int nb) {
    if (threadIdx.x == 0) {
        int acc = 0;
        for (int b = 0; b < nb; b++) { g_blockoff[b] = acc; acc += g_blocksum[b]; }
    }
}
__global__ void k_scan3() {
    int n = blockIdx.x * blockDim.x + threadIdx.x;
    if (n < NN) {
        int r = g_rowptr[n] + g_blockoff[n >> 10];
        g_rowptr[n] = r;
        g_cursor[n] = r;
    }
    if (n == 0) g_rowptr[NN] = EE;
}

// ---------------- CSR scatter: edges sorted by dst, precompute edge weight ----------------
__global__ void k_scatter(const int* __restrict__ src, const int* __restrict__ dst) {
    int e = blockIdx.x * blockDim.x + threadIdx.x;
    if (e < EE) {
        int d = dst[e], s = src[e];
        int pos = atomicAdd(&g_cursor[d], 1);
        g_colsrc[pos] = s;
        g_colw[pos]   = g_dinv[s] * g_dinv[d];
    }
}

// ---------------- tf32 tensor-core GEMM with fused LN affine on input ----------------
// Y = (a.*X + c) @ W.  BM=128, BN=128, BK=16. 256 threads = 8 warps (2x4),
// warp tile 64x32 via m16n8k8 tf32 mma (4x4 tiles).
template <int K_, int N_, bool X_FROM_H1>
__global__ __launch_bounds__(256) void k_gemm_tf32(const float* __restrict__ Xin,
                                                   const float* __restrict__ W) {
    constexpr int BM = 128, BN = 128, BK = 16;
    constexpr int LDA = 136;  // pad: conflict-free frag loads
    __shared__ uint32_t As[BK][LDA];   // [k][m], tf32 bits
    __shared__ uint32_t Bs[BK][LDA];   // [k][n], tf32 bits
    __shared__ float sA[K_], sC[K_];

    const float* __restrict__ X = X_FROM_H1 ? (const float*)g_h1 : Xin;
    float* __restrict__ Y = X_FROM_H1 ? (float*)g_h2pre : (float*)g_h1pre;

    int tid = threadIdx.x;
    for (int i = tid; i < K_; i += 256) { sA[i] = g_a[i]; sC[i] = g_c[i]; }
    __syncthreads();

    int bx = blockIdx.x, by = blockIdx.y;
    int warp = tid >> 5, lane = tid & 31;
    int wr = warp >> 2, wc = warp & 3;     // 2 x 4 warp grid
    int g  = lane >> 2, tc = lane & 3;

    float acc[4][4][4];
#pragma unroll
    for (int i = 0; i < 4; i++)
#pragma unroll
        for (int j = 0; j < 4; j++)
#pragma unroll
            for (int q = 0; q < 4; q++) acc[i][j][q] = 0.f;

    for (int k0 = 0; k0 < K_; k0 += BK) {
        // ---- load A tile: 128 rows x 16 cols, apply LN affine, cvt to tf32, transpose ----
#pragma unroll
        for (int h = 0; h < 2; h++) {
            int i = tid + h * 256;          // 0..511 float4 index
            int r  = i >> 2;                // 0..127 (row in tile)
            int cg = (i & 3) * 4;           // 0,4,8,12 (col group)
            int row = by * BM + r;
            float4 v = (row < NN) ? *(const float4*)(X + (size_t)row * K_ + k0 + cg)
                                  : make_float4(0.f, 0.f, 0.f, 0.f);
            As[cg + 0][r] = f2tf32(fmaf(sA[k0 + cg + 0], v.x, sC[k0 + cg + 0]));
            As[cg + 1][r] = f2tf32(fmaf(sA[k0 + cg + 1], v.y, sC[k0 + cg + 1]));
            As[cg + 2][r] = f2tf32(fmaf(sA[k0 + cg + 2], v.z, sC[k0 + cg + 2]));
            As[cg + 3][r] = f2tf32(fmaf(sA[k0 + cg + 3], v.w, sC[k0 + cg + 3]));
        }
        // ---- load B tile: 16 rows x 128 cols ----
#pragma unroll
        for (int h = 0; h < 2; h++) {
            int i = tid + h * 256;
            int r  = i >> 5;                // 0..15
            int c4 = (i & 31) * 4;          // 0..124
            float4 v = *(const float4*)(W + (size_t)(k0 + r) * N_ + bx * BN + c4);
            uint4 u;
            u.x = f2tf32(v.x); u.y = f2tf32(v.y); u.z = f2tf32(v.z); u.w = f2tf32(v.w);
            *(uint4*)&Bs[r][c4] = u;
        }
        __syncthreads();

#pragma unroll
        for (int ks = 0; ks < BK; ks += 8) {
            uint32_t af[4][4], bf[4][2];
#pragma unroll
            for (int mt = 0; mt < 4; mt++) {
                int mb = wr * 64 + mt * 16;
                af[mt][0] = As[ks + tc    ][mb + g    ];
                af[mt][1] = As[ks + tc    ][mb + g + 8];
                af[mt][2] = As[ks + tc + 4][mb + g    ];
                af[mt][3] = As[ks + tc + 4][mb + g + 8];
            }
#pragma unroll
            for (int nt = 0; nt < 4; nt++) {
                int nb = wc * 32 + nt * 8;
                bf[nt][0] = Bs[ks + tc    ][nb + g];
                bf[nt][1] = Bs[ks + tc + 4][nb + g];
            }
#pragma unroll
            for (int mt = 0; mt < 4; mt++)
#pragma unroll
                for (int nt = 0; nt < 4; nt++)
                    mma_tf32(acc[mt][nt], af[mt][0], af[mt][1], af[mt][2], af[mt][3],
                             bf[nt][0], bf[nt][1]);
        }
        __syncthreads();
    }

    // ---- epilogue: scatter accumulators ----
#pragma unroll
    for (int mt = 0; mt < 4; mt++) {
        int r0 = by * BM + wr * 64 + mt * 16 + g;
        int r1 = r0 + 8;
#pragma unroll
        for (int nt = 0; nt < 4; nt++) {
            int col = bx * BN + wc * 32 + nt * 8 + 2 * tc;
            if (r0 < NN) {
                float2 v0 = make_float2(acc[mt][nt][0], acc[mt][nt][1]);
                *(float2*)(Y + (size_t)r0 * N_ + col) = v0;
            }
            if (r1 < NN) {
                float2 v1 = make_float2(acc[mt][nt][2], acc[mt][nt][3]);
                *(float2*)(Y + (size_t)r1 * N_ + col) = v1;
            }
        }
    }
}

// ---------------- aggregation: float4 lanes, multiple nodes per block ----------------
// blockDim = (F/4, NPB). One (node) per threadIdx.y row of lanes. No output atomics.
template <int F, int NPB, bool SECOND>
__global__ void k_agg(const float* __restrict__ bias) {
    constexpr int F4 = F / 4;
    const float4* __restrict__ hpre = SECOND ? (const float4*)g_h2pre : (const float4*)g_h1pre;
    float4* __restrict__ hout       = SECOND ? (float4*)g_h2 : (float4*)g_h1;

    int n = blockIdx.x * NPB + threadIdx.y;
    if (n >= NN) return;
    int f = threadIdx.x;

    float di = g_dinv[n];
    float4 self = hpre[(size_t)n * F4 + f];
    float w_self = di * di;
    float4 acc;
    acc.x = w_self * self.x; acc.y = w_self * self.y;
    acc.z = w_self * self.z; acc.w = w_self * self.w;

    int e = g_rowptr[n];
    int end = g_rowptr[n + 1];
    for (; e + 4 <= end; e += 4) {
        int s0 = g_colsrc[e + 0], s1 = g_colsrc[e + 1];
        int s2 = g_colsrc[e + 2], s3 = g_colsrc[e + 3];
        float w0 = g_colw[e + 0], w1 = g_colw[e + 1];
        float w2 = g_colw[e + 2], w3 = g_colw[e + 3];
        float4 v0 = hpre[(size_t)s0 * F4 + f];
        float4 v1 = hpre[(size_t)s1 * F4 + f];
        float4 v2 = hpre[(size_t)s2 * F4 + f];
        float4 v3 = hpre[(size_t)s3 * F4 + f];
        acc.x = fmaf(w0, v0.x, acc.x); acc.y = fmaf(w0, v0.y, acc.y);
        acc.z = fmaf(w0, v0.z, acc.z); acc.w = fmaf(w0, v0.w, acc.w);
        acc.x = fmaf(w1, v1.x, acc.x); acc.y = fmaf(w1, v1.y, acc.y);
        acc.z = fmaf(w1, v1.z, acc.z); acc.w = fmaf(w1, v1.w, acc.w);
        acc.x = fmaf(w2, v2.x, acc.x); acc.y = fmaf(w2, v2.y, acc.y);
        acc.z = fmaf(w2, v2.z, acc.z); acc.w = fmaf(w2, v2.w, acc.w);
        acc.x = fmaf(w3, v3.x, acc.x); acc.y = fmaf(w3, v3.y, acc.y);
        acc.z = fmaf(w3, v3.z, acc.z); acc.w = fmaf(w3, v3.w, acc.w);
    }
    for (; e < end; ++e) {
        float w = g_colw[e];
        float4 v = hpre[(size_t)g_colsrc[e] * F4 + f];
        acc.x = fmaf(w, v.x, acc.x); acc.y = fmaf(w, v.y, acc.y);
        acc.z = fmaf(w, v.z, acc.z); acc.w = fmaf(w, v.w, acc.w);
    }

    float4 b = ((const float4*)bias)[f];
    float4 o;
    o.x = fmaxf(acc.x + b.x, 0.f);
    o.y = fmaxf(acc.y + b.y, 0.f);
    o.z = fmaxf(acc.z + b.z, 0.f);
    o.w = fmaxf(acc.w + b.w, 0.f);
    hout[(size_t)n * F4 + f] = o;
}

// ---------------- reduce h2: column sums + global sumsq ----------------
__global__ void k_reduce_h2() {
    int tid = threadIdx.x;
    float col = 0.f, ss = 0.f;
    int stride = gridDim.x * 256;     // multiple of 128 -> fixed channel per thread
    for (int i = blockIdx.x * 256 + tid; i < NN * FOUT; i += stride) {
        float v = g_h2[i];
        col += v;
        ss += v * v;
    }
    __shared__ float shc[256], shs[256];
    shc[tid] = col; shs[tid] = ss;
    __syncthreads();
    if (tid < 128) shc[tid] += shc[tid + 128];  // same channel pairing
    for (int o = 128; o > 0; o >>= 1) {
        if (tid < o) shs[tid] += shs[tid + o];
        __syncthreads();
    }
    if (tid < 128) atomicAdd(&g_colsum[tid], shc[tid]);
    if (tid == 0)  atomicAdd(&g_ss2, shs[0]);
}

// ---------------- final LN2 + global mean pool -> out[1,128] ----------------
__global__ void k_final(const float* __restrict__ w, const float* __restrict__ b,
                        float* __restrict__ out) {
    __shared__ float sh[128];
    int tid = threadIdx.x;
    float cs = g_colsum[tid];
    sh[tid] = cs;
    __syncthreads();
    for (int o = 64; o > 0; o >>= 1) {
        if (tid < o) sh[tid] += sh[tid + o];
        __syncthreads();
    }
    float invM = 1.f / (float)((size_t)NN * FOUT);
    float mean = sh[0] * invM;
    float var  = g_ss2 * invM - mean * mean;
    float rs   = rsqrtf(var + EPSF);
    out[tid] = (cs * (1.f / (float)NN) - mean) * rs * w[tid] + b[tid];
}

// ---------------- launch ----------------
extern "C" void kernel_launch(void* const* d_in, const int* in_sizes, int n_in,
                              void* d_out, int out_size) {
    const float* x    = (const float*)d_in[0];
    const int*   ei   = (const int*)d_in[1];
    const float* W1   = (const float*)d_in[2];
    const float* b1   = (const float*)d_in[3];
    const float* W2   = (const float*)d_in[4];
    const float* b2   = (const float*)d_in[5];
    const float* ln0w = (const float*)d_in[6];
    const float* ln0b = (const float*)d_in[7];
    const float* ln1w = (const float*)d_in[8];
    const float* ln1b = (const float*)d_in[9];
    const float* ln2w = (const float*)d_in[10];
    const float* ln2b = (const float*)d_in[11];
    const int* src = ei;
    const int* dst = ei + EE;
    float* out = (float*)d_out;

    dim3 nb256((NN + 255) / 256, 1, 1);
    dim3 eb256((EE + 255) / 256, 1, 1);

    // init + ln0 stats + graph structure
    k_init<<<nb256, 256>>>();
    k_stats<false><<<NBLK_STATS, 256>>>(x, (NN * FIN) / 4);
    k_deg<<<eb256, 256>>>(dst);
    k_dinv<<<nb256, 256>>>();
    k_finalize_ln<<<1, 256>>>(1.f / (float)((size_t)NN * FIN), ln0w, ln0b, FIN);
    k_scan1<<<NSCAN, SCAN_B>>>();
    k_scan2<<<1, 32>>>(NSCAN);
    k_scan3<<<nb256, 256>>>();
    k_scatter<<<eb256, 256>>>(src, dst);

    // layer 1: (ln0(x)) @ W1 (tensor cores) -> aggregate + bias + relu
    k_gemm_tf32<FIN, FHID, false><<<dim3(FHID / 128, (NN + 127) / 128), 256>>>(x, W1);
    k_agg<FHID, 2, false><<<(NN + 1) / 2, dim3(64, 2)>>>(b1);

    // ln1 stats -> affine for GEMM2
    k_stats<true><<<NBLK_STATS, 256>>>(nullptr, (NN * FHID) / 4);
    k_finalize_ln<<<1, 256>>>(1.f / (float)((size_t)NN * FHID), ln1w, ln1b, FHID);

    // layer 2: (ln1(h1)) @ W2 (tensor cores) -> aggregate + bias + relu
    k_gemm_tf32<FHID, FOUT, true><<<dim3(FOUT / 128, (NN + 127) / 128), 256>>>(nullptr, W2);
    k_agg<FOUT, 4, true><<<(NN + 3) / 4, dim3(32, 4)>>>(b2);

    // ln2 + mean pool
    k_reduce_h2<<<512, 256>>>();
    k_final<<<1, FOUT>>>(ln2w, ln2b, out);
}

// round 3
// speedup vs baseline: 2.0530x; 1.0245x over previous
#include <cuda_runtime.h>
#include <cuda_fp16.h>
#include <cuda_bf16.h>
#include <cstdint>

// Problem constants (fixed by the reference)
#define NN   50000
#define EE   1600000
#define FIN  512
#define FHID 256
#define FOUT 128
#define EPSF 1e-5f

#define NBLK_STATS 1024
#define SCAN_B 1024
#define NSCAN  ((NN + SCAN_B - 1) / SCAN_B)   // 49

// ---------------- device scratch (static, allocation-free) ----------------
__device__ __half g_h1pre[(size_t)NN * FHID];   // fp16: halves agg gather traffic
__device__ float  g_h1   [(size_t)NN * FHID];
__device__ __half g_h2pre[(size_t)NN * FOUT];
__device__ float  g_h2   [(size_t)NN * FOUT];
__device__ int   g_colsrc[EE];
__device__ float g_colw  [EE];
__device__ int   g_deg   [NN];
__device__ float g_dinv  [NN];
__device__ int   g_rowptr[NN + 1];
__device__ int   g_cursor[NN];
__device__ int   g_blocksum[64];
__device__ int   g_blockoff[64];
__device__ float g_ps [NBLK_STATS];
__device__ float g_pss[NBLK_STATS];
__device__ float g_a[FIN];   // per-k LN affine scale (max K = 512)
__device__ float g_c[FIN];   // per-k LN affine shift
__device__ float g_colsum[FOUT];
__device__ float g_ss2;

// ---------------- helpers ----------------
// split (x,y) into bf16 hi pair + bf16 lo (residual) pair, packed k-even in low half
__device__ __forceinline__ void split2(float x, float y, uint32_t& hi, uint32_t& lo) {
    __nv_bfloat162 h = __floats2bfloat162_rn(x, y);
    float rx = x - __low2float(h);
    float ry = y - __high2float(h);
    __nv_bfloat162 l = __floats2bfloat162_rn(rx, ry);
    hi = *(uint32_t*)&h;
    lo = *(uint32_t*)&l;
}

__device__ __forceinline__ void mma_bf16(float c[4], const uint32_t a[4], const uint32_t b[2]) {
    asm volatile(
        "mma.sync.aligned.m16n8k16.row.col.f32.bf16.bf16.f32 "
        "{%0,%1,%2,%3}, {%4,%5,%6,%7}, {%8,%9}, {%0,%1,%2,%3};"
        : "+f"(c[0]), "+f"(c[1]), "+f"(c[2]), "+f"(c[3])
        : "r"(a[0]), "r"(a[1]), "r"(a[2]), "r"(a[3]), "r"(b[0]), "r"(b[1]));
}

__device__ __forceinline__ float4 h4_to_f4(uint2 u) {
    float2 f0 = __half22float2(*(__half2*)&u.x);
    float2 f1 = __half22float2(*(__half2*)&u.y);
    return make_float4(f0.x, f0.y, f1.x, f1.y);
}

// ---------------- init: reset accumulators every replay ----------------
__global__ void k_init() {
    int i = blockIdx.x * blockDim.x + threadIdx.x;
    if (i < NN) g_deg[i] = 1;                 // self-loop
    if (i < FOUT) g_colsum[i] = 0.f;
    if (i == FOUT) g_ss2 = 0.f;
}

// ---------------- sum / sumsq partials (vectorized grid-stride) ----------------
template <bool FROM_H1>
__global__ void k_stats(const float* __restrict__ p_in, int n4) {
    const float* __restrict__ p = FROM_H1 ? (const float*)g_h1 : p_in;
    float s = 0.f, ss = 0.f;
    int stride = gridDim.x * blockDim.x;
    for (int i = blockIdx.x * blockDim.x + threadIdx.x; i < n4; i += stride) {
        float4 v = ((const float4*)p)[i];
        s  += v.x + v.y + v.z + v.w;
        ss += v.x * v.x + v.y * v.y + v.z * v.z + v.w * v.w;
    }
    __shared__ float sh[256], sh2[256];
    sh[threadIdx.x] = s; sh2[threadIdx.x] = ss;
    __syncthreads();
    for (int o = 128; o > 0; o >>= 1) {
        if (threadIdx.x < o) { sh[threadIdx.x] += sh[threadIdx.x + o]; sh2[threadIdx.x] += sh2[threadIdx.x + o]; }
        __syncthreads();
    }
    if (threadIdx.x == 0) { g_ps[blockIdx.x] = sh[0]; g_pss[blockIdx.x] = sh2[0]; }
}

// ---------------- finalize LN stats -> per-k affine a,c ----------------
__global__ void k_finalize_ln(float invM, const float* __restrict__ w,
                              const float* __restrict__ b, int K) {
    __shared__ float sh[256], sh2[256];
    int tid = threadIdx.x;
    float s = 0.f, ss = 0.f;
    for (int i = tid; i < NBLK_STATS; i += 256) { s += g_ps[i]; ss += g_pss[i]; }
    sh[tid] = s; sh2[tid] = ss;
    __syncthreads();
    for (int o = 128; o > 0; o >>= 1) {
        if (tid < o) { sh[tid] += sh[tid + o]; sh2[tid] += sh2[tid + o]; }
        __syncthreads();
    }
    __shared__ float smean, srs;
    if (tid == 0) {
        float mean = sh[0] * invM;
        float var  = sh2[0] * invM - mean * mean;
        smean = mean;
        srs = rsqrtf(var + EPSF);
    }
    __syncthreads();
    for (int k = tid; k < K; k += 256) {
        float wk = w[k];
        g_a[k] = srs * wk;
        g_c[k] = fmaf(-srs * smean, wk, b[k]);
    }
}

// ---------------- degree histogram ----------------
__global__ void k_deg(const int* __restrict__ dst) {
    int e = blockIdx.x * blockDim.x + threadIdx.x;
    if (e < EE) atomicAdd(&g_deg[dst[e]], 1);
}

// ---------------- exclusive scan over in-degree counts -> row_ptr ----------------
__global__ void k_scan1() {
    __shared__ int s[SCAN_B];
    int tid = threadIdx.x;
    int n = blockIdx.x * SCAN_B + tid;
    int cnt = (n < NN) ? (g_deg[n] - 1) : 0;   // exclude self-loop
    s[tid] = cnt;
    __syncthreads();
    for (int off = 1; off < SCAN_B; off <<= 1) {
        int v = (tid >= off) ? s[tid - off] : 0;
        __syncthreads();
        s[tid] += v;
        __syncthreads();
    }
    if (n < NN) g_rowptr[n] = s[tid] - cnt;     // exclusive
    if (tid == SCAN_B - 1) g_blocksum[blockIdx.x] = s[SCAN_B - 1];
}
__global__ void k_scan2(int nb) {
    if (threadIdx.x == 0) {
        int acc = 0;
        for (int b = 0; b < nb; b++) { g_blockoff[b] = acc; acc += g_blocksum[b]; }
    }
}
__global__ void k_scan3() {
    int n = blockIdx.x * blockDim.x + threadIdx.x;
    if (n < NN) {
        int r = g_rowptr[n] + g_blockoff[n >> 10];
        g_rowptr[n] = r;
        g_cursor[n] = r;
        g_dinv[n] = rsqrtf((float)g_deg[n]);    // fused (was k_dinv)
    }
    if (n == 0) g_rowptr[NN] = EE;
}

// ---------------- CSR scatter: edges sorted by dst, precompute edge weight ----------------
__global__ void k_scatter(const int* __restrict__ src, const int* __restrict__ dst) {
    int e = blockIdx.x * blockDim.x + threadIdx.x;
    if (e < EE) {
        int d = dst[e], s = src[e];
        int pos = atomicAdd(&g_cursor[d], 1);
        g_colsrc[pos] = s;
        g_colw[pos]   = g_dinv[s] * g_dinv[d];
    }
}

// ---------------- bf16x3 tensor-core GEMM with fused LN affine on input ----------------
// Y = (a.*X + c) @ W, fp32-accurate via bf16 hi/lo split (3 MMAs per tile).
// BM=128, BN=128, BK=16. 256 threads = 8 warps (2x4), warp tile 64x32,
// m16n8k16 bf16 mma. Output written as fp16.
template <int K_, int N_, bool X_FROM_H1>
__global__ __launch_bounds__(256) void k_gemm_bf16x3(const float* __restrict__ Xin,
                                                     const float* __restrict__ W) {
    constexpr int BM = 128, BN = 128, BK = 16;
    constexpr int BK2 = BK / 2;       // packed k-pair rows
    constexpr int LDA = 136;
    __shared__ uint32_t As_hi[BK2][LDA];   // [k2][m], bf16x2 (k even low)
    __shared__ uint32_t As_lo[BK2][LDA];
    __shared__ uint32_t Bs_hi[BK2][LDA];   // [k2][n]
    __shared__ uint32_t Bs_lo[BK2][LDA];
    __shared__ float sA[K_], sC[K_];

    const float* __restrict__ X = X_FROM_H1 ? (const float*)g_h1 : Xin;
    __half* __restrict__ Y = X_FROM_H1 ? (__half*)g_h2pre : (__half*)g_h1pre;

    int tid = threadIdx.x;
    for (int i = tid; i < K_; i += 256) { sA[i] = g_a[i]; sC[i] = g_c[i]; }
    __syncthreads();

    int bx = blockIdx.x, by = blockIdx.y;
    int warp = tid >> 5, lane = tid & 31;
    int wr = warp >> 2, wc = warp & 3;     // 2 x 4 warp grid
    int g  = lane >> 2, tc = lane & 3;

    float acc[4][4][4];
#pragma unroll
    for (int i = 0; i < 4; i++)
#pragma unroll
        for (int j = 0; j < 4; j++)
#pragma unroll
            for (int q = 0; q < 4; q++) acc[i][j][q] = 0.f;

    for (int k0 = 0; k0 < K_; k0 += BK) {
        // ---- A tile: 128 rows x 16 k, LN affine, bf16 hi/lo split, transpose ----
#pragma unroll
        for (int h = 0; h < 2; h++) {
            int i = tid + h * 256;          // 0..511 float4 index
            int r   = i >> 2;               // 0..127 (row in tile)
            int cg  = (i & 3) * 4;          // 0,4,8,12 (k offset)
            int cg2 = cg >> 1;              // packed k2 index
            int row = by * BM + r;
            float4 v = (row < NN) ? *(const float4*)(X + (size_t)row * K_ + k0 + cg)
                                  : make_float4(0.f, 0.f, 0.f, 0.f);
            float f0 = fmaf(sA[k0 + cg + 0], v.x, sC[k0 + cg + 0]);
            float f1 = fmaf(sA[k0 + cg + 1], v.y, sC[k0 + cg + 1]);
            float f2 = fmaf(sA[k0 + cg + 2], v.z, sC[k0 + cg + 2]);
            float f3 = fmaf(sA[k0 + cg + 3], v.w, sC[k0 + cg + 3]);
            uint32_t h0, l0, h1, l1;
            split2(f0, f1, h0, l0);
            split2(f2, f3, h1, l1);
            As_hi[cg2    ][r] = h0; As_lo[cg2    ][r] = l0;
            As_hi[cg2 + 1][r] = h1; As_lo[cg2 + 1][r] = l1;
        }
        // ---- B tile: 16 k-rows x 128 cols, pack adjacent k rows ----
        {
            int k2 = tid >> 5;              // 0..7
            int c4 = (tid & 31) * 4;        // 0..124
            const float* Wp = W + (size_t)(k0 + 2 * k2) * N_ + bx * BN + c4;
            float4 v0 = *(const float4*)Wp;          // k even
            float4 v1 = *(const float4*)(Wp + N_);   // k odd
            uint4 uh, ul;
            split2(v0.x, v1.x, uh.x, ul.x);
            split2(v0.y, v1.y, uh.y, ul.y);
            split2(v0.z, v1.z, uh.z, ul.z);
            split2(v0.w, v1.w, uh.w, ul.w);
            *(uint4*)&Bs_hi[k2][c4] = uh;
            *(uint4*)&Bs_lo[k2][c4] = ul;
        }
        __syncthreads();

        uint32_t ah[4][4], al[4][4], bh[4][2], bl[4][2];
#pragma unroll
        for (int mt = 0; mt < 4; mt++) {
            int mb = wr * 64 + mt * 16;
            ah[mt][0] = As_hi[tc    ][mb + g    ];
            ah[mt][1] = As_hi[tc    ][mb + g + 8];
            ah[mt][2] = As_hi[tc + 4][mb + g    ];
            ah[mt][3] = As_hi[tc + 4][mb + g + 8];
            al[mt][0] = As_lo[tc    ][mb + g    ];
            al[mt][1] = As_lo[tc    ][mb + g + 8];
            al[mt][2] = As_lo[tc + 4][mb + g    ];
            al[mt][3] = As_lo[tc + 4][mb + g + 8];
        }
#pragma unroll
        for (int nt = 0; nt < 4; nt++) {
            int nb = wc * 32 + nt * 8;
            bh[nt][0] = Bs_hi[tc    ][nb + g];
            bh[nt][1] = Bs_hi[tc + 4][nb + g];
            bl[nt][0] = Bs_lo[tc    ][nb + g];
            bl[nt][1] = Bs_lo[tc + 4][nb + g];
        }
#pragma unroll
        for (int mt = 0; mt < 4; mt++)
#pragma unroll
            for (int nt = 0; nt < 4; nt++) {
                mma_bf16(acc[mt][nt], ah[mt], bh[nt]);
                mma_bf16(acc[mt][nt], ah[mt], bl[nt]);
                mma_bf16(acc[mt][nt], al[mt], bh[nt]);
            }
        __syncthreads();
    }

    // ---- epilogue: fp16 stores ----
#pragma unroll
    for (int mt = 0; mt < 4; mt++) {
        int r0 = by * BM + wr * 64 + mt * 16 + g;
        int r1 = r0 + 8;
#pragma unroll
        for (int nt = 0; nt < 4; nt++) {
            int col = bx * BN + wc * 32 + nt * 8 + 2 * tc;
            if (r0 < NN)
                *(__half2*)(Y + (size_t)r0 * N_ + col) = __floats2half2_rn(acc[mt][nt][0], acc[mt][nt][1]);
            if (r1 < NN)
                *(__half2*)(Y + (size_t)r1 * N_ + col) = __floats2half2_rn(acc[mt][nt][2], acc[mt][nt][3]);
        }
    }
}

// ---------------- aggregation: fp16 gathers (uint2 = 4 halves per lane) ----------------
// blockDim = (F/4, NPB). One node per threadIdx.y. No output atomics.
template <int F, int NPB, bool SECOND>
__global__ void k_agg(const float* __restrict__ bias) {
    constexpr int F4 = F / 4;   // uint2 elements per row
    const uint2* __restrict__ hpre = SECOND ? (const uint2*)g_h2pre : (const uint2*)g_h1pre;
    float4* __restrict__ hout      = SECOND ? (float4*)g_h2 : (float4*)g_h1;

    int n = blockIdx.x * NPB + threadIdx.y;
    if (n >= NN) return;
    int f = threadIdx.x;

    float di = g_dinv[n];
    float4 self = h4_to_f4(hpre[(size_t)n * F4 + f]);
    float w_self = di * di;
    float4 acc;
    acc.x = w_self * self.x; acc.y = w_self * self.y;
    acc.z = w_self * self.z; acc.w = w_self * self.w;

    int e = g_rowptr[n];
    int end = g_rowptr[n + 1];
    for (; e + 4 <= end; e += 4) {
        int s0 = g_colsrc[e + 0], s1 = g_colsrc[e + 1];
        int s2 = g_colsrc[e + 2], s3 = g_colsrc[e + 3];
        float w0 = g_colw[e + 0], w1 = g_colw[e + 1];
        float w2 = g_colw[e + 2], w3 = g_colw[e + 3];
        float4 v0 = h4_to_f4(hpre[(size_t)s0 * F4 + f]);
        float4 v1 = h4_to_f4(hpre[(size_t)s1 * F4 + f]);
        float4 v2 = h4_to_f4(hpre[(size_t)s2 * F4 + f]);
        float4 v3 = h4_to_f4(hpre[(size_t)s3 * F4 + f]);
        acc.x = fmaf(w0, v0.x, acc.x); acc.y = fmaf(w0, v0.y, acc.y);
        acc.z = fmaf(w0, v0.z, acc.z); acc.w = fmaf(w0, v0.w, acc.w);
        acc.x = fmaf(w1, v1.x, acc.x); acc.y = fmaf(w1, v1.y, acc.y);
        acc.z = fmaf(w1, v1.z, acc.z); acc.w = fmaf(w1, v1.w, acc.w);
        acc.x = fmaf(w2, v2.x, acc.x); acc.y = fmaf(w2, v2.y, acc.y);
        acc.z = fmaf(w2, v2.z, acc.z); acc.w = fmaf(w2, v2.w, acc.w);
        acc.x = fmaf(w3, v3.x, acc.x); acc.y = fmaf(w3, v3.y, acc.y);
        acc.z = fmaf(w3, v3.z, acc.z); acc.w = fmaf(w3, v3.w, acc.w);
    }
    for (; e < end; ++e) {
        float w = g_colw[e];
        float4 v = h4_to_f4(hpre[(size_t)g_colsrc[e] * F4 + f]);
        acc.x = fmaf(w, v.x, acc.x); acc.y = fmaf(w, v.y, acc.y);
        acc.z = fmaf(w, v.z, acc.z); acc.w = fmaf(w, v.w, acc.w);
    }

    float4 b = ((const float4*)bias)[f];
    float4 o;
    o.x = fmaxf(acc.x + b.x, 0.f);
    o.y = fmaxf(acc.y + b.y, 0.f);
    o.z = fmaxf(acc.z + b.z, 0.f);
    o.w = fmaxf(acc.w + b.w, 0.f);
    hout[(size_t)n * F4 + f] = o;
}

// ---------------- reduce h2: column sums + global sumsq ----------------
__global__ void k_reduce_h2() {
    int tid = threadIdx.x;
    float col = 0.f, ss = 0.f;
    int stride = gridDim.x * 256;     // multiple of 128 -> fixed channel per thread
    for (int i = blockIdx.x * 256 + tid; i < NN * FOUT; i += stride) {
        float v = g_h2[i];
        col += v;
        ss += v * v;
    }
    __shared__ float shc[256], shs[256];
    shc[tid] = col; shs[tid] = ss;
    __syncthreads();
    if (tid < 128) shc[tid] += shc[tid + 128];  // same channel pairing
    for (int o = 128; o > 0; o >>= 1) {
        if (tid < o) shs[tid] += shs[tid + o];
        __syncthreads();
    }
    if (tid < 128) atomicAdd(&g_colsum[tid], shc[tid]);
    if (tid == 0)  atomicAdd(&g_ss2, shs[0]);
}

// ---------------- final LN2 + global mean pool -> out[1,128] ----------------
__global__ void k_final(const float* __restrict__ w, const float* __restrict__ b,
                        float* __restrict__ out) {
    __shared__ float sh[128];
    int tid = threadIdx.x;
    float cs = g_colsum[tid];
    sh[tid] = cs;
    __syncthreads();
    for (int o = 64; o > 0; o >>= 1) {
        if (tid < o) sh[tid] += sh[tid + o];
        __syncthreads();
    }
    float invM = 1.f / (float)((size_t)NN * FOUT);
    float mean = sh[0] * invM;
    float var  = g_ss2 * invM - mean * mean;
    float rs   = rsqrtf(var + EPSF);
    out[tid] = (cs * (1.f / (float)NN) - mean) * rs * w[tid] + b[tid];
}

// ---------------- launch ----------------
extern "C" void kernel_launch(void* const* d_in, const int* in_sizes, int n_in,
                              void* d_out, int out_size) {
    const float* x    = (const float*)d_in[0];
    const int*   ei   = (const int*)d_in[1];
    const float* W1   = (const float*)d_in[2];
    const float* b1   = (const float*)d_in[3];
    const float* W2   = (const float*)d_in[4];
    const float* b2   = (const float*)d_in[5];
    const float* ln0w = (const float*)d_in[6];
    const float* ln0b = (const float*)d_in[7];
    const float* ln1w = (const float*)d_in[8];
    const float* ln1b = (const float*)d_in[9];
    const float* ln2w = (const float*)d_in[10];
    const float* ln2b = (const float*)d_in[11];
    const int* src = ei;
    const int* dst = ei + EE;
    float* out = (float*)d_out;

    dim3 nb256((NN + 255) / 256, 1, 1);
    dim3 eb256((EE + 255) / 256, 1, 1);

    // init + ln0 stats + graph structure
    k_init<<<nb256, 256>>>();
    k_stats<false><<<NBLK_STATS, 256>>>(x, (NN * FIN) / 4);
    k_deg<<<eb256, 256>>>(dst);
    k_finalize_ln<<<1, 256>>>(1.f / (float)((size_t)NN * FIN), ln0w, ln0b, FIN);
    k_scan1<<<NSCAN, SCAN_B>>>();
    k_scan2<<<1, 32>>>(NSCAN);
    k_scan3<<<nb256, 256>>>();
    k_scatter<<<eb256, 256>>>(src, dst);

    // layer 1: (ln0(x)) @ W1 (bf16x3 tensor cores) -> aggregate + bias + relu
    k_gemm_bf16x3<FIN, FHID, false><<<dim3(FHID / 128, (NN + 127) / 128), 256>>>(x, W1);
    k_agg<FHID, 2, false><<<(NN + 1) / 2, dim3(64, 2)>>>(b1);

    // ln1 stats -> affine for GEMM2
    k_stats<true><<<NBLK_STATS, 256>>>(nullptr, (NN * FHID) / 4);
    k_finalize_ln<<<1, 256>>>(1.f / (float)((size_t)NN * FHID), ln1w, ln1b, FHID);

    // layer 2: (ln1(h1)) @ W2 (bf16x3 tensor cores) -> aggregate + bias + relu
    k_gemm_bf16x3<FHID, FOUT, true><<<dim3(FOUT / 128, (NN + 127) / 128), 256>>>(nullptr, W2);
    k_agg<FOUT, 4, true><<<(NN + 3) / 4, dim3(32, 4)>>>(b2);

    // ln2 + mean pool
    k_reduce_h2<<<512, 256>>>();
    k_final<<<1, FOUT>>>(ln2w, ln2b, out);
}